// round 2
// baseline (speedup 1.0000x reference)
#include <cuda_runtime.h>
#include <math.h>

#define BDIM 32
#define TDIM 32
#define IDIM 256
#define HDIM 512
#define HS 64
#define MS 2048
#define NHEADS 4
#define ODIM 256

// ---------------- persistent state (no allocations allowed) ----------------
__device__ float g_h[2][BDIM * HDIM];        // double-buffered hidden state
__device__ float g_c[BDIM * HDIM];           // cell state (thread-private RMW)
__device__ float g_read[BDIM * NHEADS * HS]; // read vectors
__device__ float g_rk[BDIM * NHEADS * HS];   // read keys
__device__ float g_wk[BDIM * NHEADS * HS];   // write keys
__device__ float g_ws[BDIM * NHEADS];        // sigmoid(write strength)
__device__ float g_logits[BDIM * 2 * NHEADS * MS];
__device__ float g_rw[BDIM * NHEADS * MS];
__device__ float g_ww[BDIM * NHEADS * MS];
__device__ float g_rpart[BDIM * 32 * NHEADS * HS]; // per-chunk read partials

__device__ __forceinline__ float sigmoidf_(float x) { return 1.f / (1.f + expf(-x)); }

// ---------------- init: zero h0, c0, read0, mem0 ----------------
__global__ void k_init(float* __restrict__ mem) {
    int idx = blockIdx.x * 256 + threadIdx.x;
    if (idx < BDIM * HDIM) { g_h[0][idx] = 0.f; g_c[idx] = 0.f; }
    if (idx < BDIM * NHEADS * HS) g_read[idx] = 0.f;
    if (idx < BDIM * MS * HS) mem[idx] = 0.f;
}

// ---------------- K1: fused gate GEMM + LSTM cell ----------------
// gates(b, g*512+j) = sum_k cat[b,k] * Wcat[g*512+j, k],  cat = [x_t | read | h]
// warp = one j (all 4 gates) x 8 batches; lane owns 4 consecutive k per chunk.
__global__ void __launch_bounds__(256) k_lstm(
    const float* __restrict__ x, const float* __restrict__ W_ih,
    const float* __restrict__ W_hh, const float* __restrict__ b_ih,
    const float* __restrict__ b_hh, int p, int t)
{
    __shared__ float inp_s[8][1024];
    const float* __restrict__ h_prev = g_h[p];
    float* __restrict__ h_new = g_h[p ^ 1];
    int tid = threadIdx.x;
    int bb0 = blockIdx.y * 8;
    for (int idx = tid; idx < 8 * 1024; idx += 256) {
        int bb = idx >> 10, k = idx & 1023;
        int b = bb0 + bb;
        float v;
        if (k < 256)      v = x[(b * TDIM + t) * IDIM + k];
        else if (k < 512) v = g_read[b * 256 + (k - 256)];
        else              v = h_prev[b * HDIM + (k - 512)];
        inp_s[bb][k] = v;
    }
    __syncthreads();
    int w = tid >> 5, lane = tid & 31;
    int j = blockIdx.x * 8 + w;
    float acc[4][8];
#pragma unroll
    for (int g = 0; g < 4; g++)
#pragma unroll
        for (int bb = 0; bb < 8; bb++) acc[g][bb] = 0.f;

#pragma unroll
    for (int c = 0; c < 8; c++) {
        const float* Wsrc = (c < 4) ? W_ih : W_hh;
        int kw = ((c & 3) * 128) + lane * 4;   // offset within the 512-wide W row
        float4 w4[4];
#pragma unroll
        for (int g = 0; g < 4; g++)
            w4[g] = *(const float4*)&Wsrc[(size_t)(g * HDIM + j) * HDIM + kw];
        int ks = c * 128 + lane * 4;           // offset within the 1024-wide cat row
#pragma unroll
        for (int bb = 0; bb < 8; bb++) {
            float4 a4 = *(const float4*)&inp_s[bb][ks];
#pragma unroll
            for (int g = 0; g < 4; g++) {
                acc[g][bb] = fmaf(w4[g].x, a4.x, acc[g][bb]);
                acc[g][bb] = fmaf(w4[g].y, a4.y, acc[g][bb]);
                acc[g][bb] = fmaf(w4[g].z, a4.z, acc[g][bb]);
                acc[g][bb] = fmaf(w4[g].w, a4.w, acc[g][bb]);
            }
        }
    }
    // cross-lane reduce; lane g*8+bb ends up holding gate g of batch bb
    float res = 0.f;
#pragma unroll
    for (int g = 0; g < 4; g++)
#pragma unroll
        for (int bb = 0; bb < 8; bb++) {
            float v = acc[g][bb];
            v += __shfl_xor_sync(0xffffffffu, v, 16);
            v += __shfl_xor_sync(0xffffffffu, v, 8);
            v += __shfl_xor_sync(0xffffffffu, v, 4);
            v += __shfl_xor_sync(0xffffffffu, v, 2);
            v += __shfl_xor_sync(0xffffffffu, v, 1);
            if (lane == g * 8 + bb) res = v;
        }
    int bb = lane & 7;
    float iv = __shfl_sync(0xffffffffu, res, bb);
    float fv = __shfl_sync(0xffffffffu, res, 8 + bb);
    float gv = __shfl_sync(0xffffffffu, res, 16 + bb);
    float ov = __shfl_sync(0xffffffffu, res, 24 + bb);
    if (lane < 8) {
        int b = bb0 + lane;
        iv += b_ih[j] + b_hh[j];
        fv += b_ih[HDIM + j] + b_hh[HDIM + j];
        gv += b_ih[2 * HDIM + j] + b_hh[2 * HDIM + j];
        ov += b_ih[3 * HDIM + j] + b_hh[3 * HDIM + j];
        float cold = g_c[b * HDIM + j];
        float cn = sigmoidf_(fv) * cold + sigmoidf_(iv) * tanhf(gv);
        float hn = sigmoidf_(ov) * tanhf(cn);
        g_c[b * HDIM + j] = cn;
        h_new[b * HDIM + j] = hn;
    }
}

// ---------------- K2: head projection, ONLY the 129 used columns per head ----------------
__global__ void __launch_bounds__(256) k_head(
    const float* __restrict__ W_head, const float* __restrict__ b_head, int pn)
{
    __shared__ float h_s[8][512];
    const float* __restrict__ h_new = g_h[pn];
    int tid = threadIdx.x;
    int bb0 = blockIdx.y * 8;
    for (int idx = tid; idx < 8 * 512; idx += 256) {
        int bb = idx >> 9, k = idx & 511;
        h_s[bb][k] = h_new[(bb0 + bb) * HDIM + k];
    }
    __syncthreads();
    int w = tid >> 5, lane = tid & 31;
    int r = blockIdx.x * 8 + w;
    if (r >= NHEADS * 129) return;
    int n = r / 129, jj = r % 129;
    int wrow = n * 2115 + jj;
    float acc[8];
#pragma unroll
    for (int bb = 0; bb < 8; bb++) acc[bb] = 0.f;
#pragma unroll
    for (int c = 0; c < 4; c++) {
        int kw = c * 128 + lane * 4;
        float4 w4 = *(const float4*)&W_head[(size_t)wrow * HDIM + kw];
#pragma unroll
        for (int bb = 0; bb < 8; bb++) {
            float4 a4 = *(const float4*)&h_s[bb][kw];
            acc[bb] = fmaf(w4.x, a4.x, acc[bb]);
            acc[bb] = fmaf(w4.y, a4.y, acc[bb]);
            acc[bb] = fmaf(w4.z, a4.z, acc[bb]);
            acc[bb] = fmaf(w4.w, a4.w, acc[bb]);
        }
    }
    float res = 0.f;
#pragma unroll
    for (int bb = 0; bb < 8; bb++) {
        float v = acc[bb];
        v += __shfl_xor_sync(0xffffffffu, v, 16);
        v += __shfl_xor_sync(0xffffffffu, v, 8);
        v += __shfl_xor_sync(0xffffffffu, v, 4);
        v += __shfl_xor_sync(0xffffffffu, v, 2);
        v += __shfl_xor_sync(0xffffffffu, v, 1);
        if (lane == bb) res = v;
    }
    if (lane < 8) {
        int b = bb0 + lane;
        float val = res + b_head[wrow];
        if (jj < HS)          g_rk[(b * NHEADS + n) * HS + jj] = val;
        else if (jj < 2 * HS) g_wk[(b * NHEADS + n) * HS + (jj - HS)] = val;
        else                  g_ws[b * NHEADS + n] = sigmoidf_(val);
    }
}

// ---------------- K3a: attention logits for all 8 keys (4 read + 4 write) ----------------
__global__ void __launch_bounds__(256) k_logits(const float* __restrict__ mem)
{
    __shared__ float key_s[8][64];
    int tid = threadIdx.x;
    int b = blockIdx.y;
    for (int idx = tid; idx < 512; idx += 256) {
        int key = idx >> 6, h = idx & 63, n = key & 3;
        key_s[key][h] = (key < 4) ? g_rk[(b * NHEADS + n) * HS + h]
                                  : g_wk[(b * NHEADS + n) * HS + h];
    }
    __syncthreads();
    int kg = tid >> 7;                     // 0: read keys, 1: write keys
    int m = blockIdx.x * 128 + (tid & 127);
    float acc[4] = {0.f, 0.f, 0.f, 0.f};
    const float* mrow = &mem[((size_t)b * MS + m) * HS];
#pragma unroll
    for (int hq = 0; hq < 16; hq++) {
        float4 v = *(const float4*)&mrow[hq * 4];
#pragma unroll
        for (int kk = 0; kk < 4; kk++) {
            int key = kg * 4 + kk;
            acc[kk] = fmaf(v.x, key_s[key][hq * 4 + 0], acc[kk]);
            acc[kk] = fmaf(v.y, key_s[key][hq * 4 + 1], acc[kk]);
            acc[kk] = fmaf(v.z, key_s[key][hq * 4 + 2], acc[kk]);
            acc[kk] = fmaf(v.w, key_s[key][hq * 4 + 3], acc[kk]);
        }
    }
    const float scale = 0.125f;            // 1/sqrt(64)
#pragma unroll
    for (int kk = 0; kk < 4; kk++)
        g_logits[((size_t)b * 8 + kg * 4 + kk) * MS + m] = acc[kk] * scale;
}

// ---------------- K3b: softmax over m=2048 for each (b, key) ----------------
__global__ void __launch_bounds__(256) k_softmax()
{
    __shared__ float red[256];
    int tid = threadIdx.x;
    int key = blockIdx.x, b = blockIdx.y;
    const float* lg = &g_logits[((size_t)b * 8 + key) * MS];
    float vals[8];
    float lm = -1e30f;
#pragma unroll
    for (int i = 0; i < 8; i++) { vals[i] = lg[i * 256 + tid]; lm = fmaxf(lm, vals[i]); }
    red[tid] = lm; __syncthreads();
    for (int s = 128; s > 0; s >>= 1) { if (tid < s) red[tid] = fmaxf(red[tid], red[tid + s]); __syncthreads(); }
    float gmax = red[0]; __syncthreads();
    float ls = 0.f;
#pragma unroll
    for (int i = 0; i < 8; i++) { vals[i] = expf(vals[i] - gmax); ls += vals[i]; }
    red[tid] = ls; __syncthreads();
    for (int s = 128; s > 0; s >>= 1) { if (tid < s) red[tid] += red[tid + s]; __syncthreads(); }
    float inv = 1.f / red[0];
    float* dst = (key < 4) ? &g_rw[((size_t)b * NHEADS + key) * MS]
                           : &g_ww[((size_t)b * NHEADS + (key - 4)) * MS];
#pragma unroll
    for (int i = 0; i < 8; i++) dst[i * 256 + tid] = vals[i] * inv;
}

// ---------------- K4: fused read-partials + memory write-update ----------------
// Each block owns 64 mem rows of one batch: reads OLD rows for the read partial,
// then (after a block sync) updates the same rows. Disjoint rows across blocks -> safe.
__global__ void __launch_bounds__(256) k_attend(float* __restrict__ mem)
{
    __shared__ float swk_s[4][64];
    __shared__ float sred[4][256];
    int tid = threadIdx.x;
    int chunk = blockIdx.x, b = blockIdx.y;
    {
        int n = tid >> 6, h = tid & 63;
        swk_s[n][h] = g_ws[b * NHEADS + n] * g_wk[(b * NHEADS + n) * HS + h];
    }
    __syncthreads();
    int h = tid & 63, ms = tid >> 6;
    float acc[4] = {0.f, 0.f, 0.f, 0.f};
#pragma unroll
    for (int mi = 0; mi < 16; mi++) {
        int m = chunk * 64 + mi * 4 + ms;
        float v = mem[((size_t)b * MS + m) * HS + h];
#pragma unroll
        for (int n = 0; n < 4; n++)
            acc[n] = fmaf(g_rw[((size_t)b * NHEADS + n) * MS + m], v, acc[n]);
    }
#pragma unroll
    for (int n = 0; n < 4; n++) sred[ms][n * 64 + h] = acc[n];
    __syncthreads();   // also guarantees all old-mem reads are done before updates
    {
        float tot = sred[0][tid] + sred[1][tid] + sred[2][tid] + sred[3][tid];
        g_rpart[((size_t)b * 32 + chunk) * 256 + tid] = tot;
    }
    for (int idx = tid; idx < 64 * 64; idx += 256) {
        int ml = idx >> 6, hh = idx & 63;
        int m = chunk * 64 + ml;
        float val = 0.f;
#pragma unroll
        for (int n = 0; n < 4; n++)
            val = fmaf(g_ww[((size_t)b * NHEADS + n) * MS + m], swk_s[n][hh], val);
        mem[((size_t)b * MS + m) * HS + hh] += val;
    }
}

// ---------------- K4b: deterministic reduction of read partials ----------------
__global__ void __launch_bounds__(256) k_read_reduce()
{
    int tid = threadIdx.x, b = blockIdx.x;
    float s = 0.f;
#pragma unroll
    for (int ch = 0; ch < 32; ch++) s += g_rpart[((size_t)b * 32 + ch) * 256 + tid];
    g_read[b * 256 + tid] = s;
}

// ---------------- K5: output projection ----------------
__global__ void __launch_bounds__(256) k_out(
    const float* __restrict__ W_out, const float* __restrict__ b_out,
    float* __restrict__ out, int pn, int t)
{
    __shared__ float cat_s[8][768];
    const float* __restrict__ h_new = g_h[pn];
    int tid = threadIdx.x;
    int bb0 = blockIdx.y * 8;
    for (int idx = tid; idx < 8 * 768; idx += 256) {
        int bb = idx / 768, k = idx % 768;
        cat_s[bb][k] = (k < 512) ? h_new[(bb0 + bb) * HDIM + k]
                                 : g_read[(bb0 + bb) * 256 + (k - 512)];
    }
    __syncthreads();
    int w = tid >> 5, lane = tid & 31;
    int o = blockIdx.x * 8 + w;
    float acc[8];
#pragma unroll
    for (int bb = 0; bb < 8; bb++) acc[bb] = 0.f;
#pragma unroll
    for (int c = 0; c < 6; c++) {
        int kw = c * 128 + lane * 4;
        float4 w4 = *(const float4*)&W_out[(size_t)o * 768 + kw];
#pragma unroll
        for (int bb = 0; bb < 8; bb++) {
            float4 a4 = *(const float4*)&cat_s[bb][kw];
            acc[bb] = fmaf(w4.x, a4.x, acc[bb]);
            acc[bb] = fmaf(w4.y, a4.y, acc[bb]);
            acc[bb] = fmaf(w4.z, a4.z, acc[bb]);
            acc[bb] = fmaf(w4.w, a4.w, acc[bb]);
        }
    }
    float res = 0.f;
#pragma unroll
    for (int bb = 0; bb < 8; bb++) {
        float v = acc[bb];
        v += __shfl_xor_sync(0xffffffffu, v, 16);
        v += __shfl_xor_sync(0xffffffffu, v, 8);
        v += __shfl_xor_sync(0xffffffffu, v, 4);
        v += __shfl_xor_sync(0xffffffffu, v, 2);
        v += __shfl_xor_sync(0xffffffffu, v, 1);
        if (lane == bb) res = v;
    }
    if (lane < 8) {
        int b = bb0 + lane;
        out[((size_t)b * TDIM + t) * ODIM + o] = res + b_out[o];
    }
}

// ---------------- final: copy (h, c) into the output tail ----------------
__global__ void k_final(float* __restrict__ dst_h, float* __restrict__ dst_c)
{
    int idx = blockIdx.x * 256 + threadIdx.x;
    if (idx < BDIM * HDIM) {
        dst_h[idx] = g_h[0][idx];   // after 32 steps, h lives in buffer 0
        dst_c[idx] = g_c[idx];
    }
}

// ---------------- launch ----------------
extern "C" void kernel_launch(void* const* d_in, const int* in_sizes, int n_in,
                              void* d_out, int out_size)
{
    const float* x      = (const float*)d_in[0];
    const float* W_ih   = (const float*)d_in[1];
    const float* W_hh   = (const float*)d_in[2];
    const float* b_ih   = (const float*)d_in[3];
    const float* b_hh   = (const float*)d_in[4];
    const float* W_head = (const float*)d_in[5];
    const float* b_head = (const float*)d_in[6];
    const float* W_out  = (const float*)d_in[7];
    const float* b_out  = (const float*)d_in[8];

    float* out   = (float*)d_out;                 // (B, T, O)
    float* mem   = out + BDIM * TDIM * ODIM;      // (B, MS, HS) — state lives in-place
    float* out_h = mem + (size_t)BDIM * MS * HS;  // (B, H)
    float* out_c = out_h + BDIM * HDIM;           // (B, H)

    k_init<<<(BDIM * MS * HS) / 256, 256>>>(mem);

    for (int t = 0; t < TDIM; t++) {
        int p = t & 1;          // h_prev buffer
        int pn = p ^ 1;         // h_new buffer
        k_lstm<<<dim3(64, 4), 256>>>(x, W_ih, W_hh, b_ih, b_hh, p, t);
        k_head<<<dim3(65, 4), 256>>>(W_head, b_head, pn);
        k_logits<<<dim3(16, 32), 256>>>(mem);
        k_softmax<<<dim3(8, 32), 256>>>();
        k_attend<<<dim3(32, 32), 256>>>(mem);
        k_read_reduce<<<32, 256>>>();
        k_out<<<dim3(32, 4), 256>>>(W_out, b_out, out, pn, t);
    }
    k_final<<<128, 256>>>(out_h, out_c);
}